// round 16
// baseline (speedup 1.0000x reference)
#include <cuda_runtime.h>
#include <cuda_bf16.h>
#include <mma.h>
#include <math.h>

using namespace nvcuda;

#define BATCH 2
#define C 256
#define HW 65536
#define NH 16
#define DH 16

typedef unsigned long long u64;

__device__ __forceinline__ u64 ffma2(u64 a, u64 b, u64 c) {
  u64 d;
  asm("fma.rn.f32x2 %0, %1, %2, %3;" : "=l"(d) : "l"(a), "l"(b), "l"(c));
  return d;
}
__device__ __forceinline__ u64 dup2(float v) {
  u64 d;
  asm("mov.b64 %0, {%1, %1};" : "=l"(d) : "r"(__float_as_uint(v)));
  return d;
}

// Scratch (device globals — no allocation allowed)
__device__ float g_qkv[(size_t)BATCH * 3 * C * HW];
__device__ float g_o  [(size_t)BATCH * C * HW];
__device__ float g_xy [(size_t)BATCH * C * HW];
__device__ float g_bn [(size_t)BATCH * C * HW];

// ---------------------------------------------------------------------------
// Packed-f32x2 SGEMM (K=256 1x1 convs) — unchanged from R14 (verified).
// ---------------------------------------------------------------------------
__global__ __launch_bounds__(256, 2) void k_gemm0(
    const float* __restrict__ A0, const float* __restrict__ X,
    float* __restrict__ Y, int OC) {
  constexpr int K = 256;
  __shared__ float Asd[16][256];
  __shared__ float Bs[16][128];
  const int b = blockIdx.z;
  const float* Xb = X + (size_t)b * C * HW;
  float* Yb = Y + (size_t)b * OC * HW;
  const int m0 = blockIdx.x * 128;
  const int p0 = blockIdx.y * 128;
  const int tid = threadIdx.x;
  const int tx = tid & 15, ty = tid >> 4;
  const int am = tid >> 1, aq = (tid & 1) * 8;
  const int bk = tid >> 4, bn = (tid & 15) * 8;

  u64 acc[8][4];
#pragma unroll
  for (int i = 0; i < 8; i++)
#pragma unroll
    for (int j = 0; j < 4; j++) acc[i][j] = 0ull;

  for (int k0 = 0; k0 < K; k0 += 16) {
    {
      const float* src = A0 + (size_t)(m0 + am) * K + k0 + aq;
      float4 v0 = *(const float4*)src;
      float4 v1 = *(const float4*)(src + 4);
      *(u64*)&Asd[aq + 0][2 * am] = dup2(v0.x);
      *(u64*)&Asd[aq + 1][2 * am] = dup2(v0.y);
      *(u64*)&Asd[aq + 2][2 * am] = dup2(v0.z);
      *(u64*)&Asd[aq + 3][2 * am] = dup2(v0.w);
      *(u64*)&Asd[aq + 4][2 * am] = dup2(v1.x);
      *(u64*)&Asd[aq + 5][2 * am] = dup2(v1.y);
      *(u64*)&Asd[aq + 6][2 * am] = dup2(v1.z);
      *(u64*)&Asd[aq + 7][2 * am] = dup2(v1.w);
    }
    {
      const float* src = Xb + (size_t)(k0 + bk) * HW + p0 + bn;
      *(float4*)&Bs[bk][bn]     = *(const float4*)src;
      *(float4*)&Bs[bk][bn + 4] = *(const float4*)(src + 4);
    }
    __syncthreads();
#pragma unroll
    for (int k = 0; k < 16; k++) {
      const ulonglong2* ar2 = (const ulonglong2*)&Asd[k][ty * 16];
      const ulonglong2* br2 = (const ulonglong2*)&Bs[k][tx * 8];
      ulonglong2 q0 = ar2[0], q1 = ar2[1], q2 = ar2[2], q3 = ar2[3];
      ulonglong2 r0 = br2[0], r1 = br2[1];
      u64 ap[8] = {q0.x, q0.y, q1.x, q1.y, q2.x, q2.y, q3.x, q3.y};
      u64 bp[4] = {r0.x, r0.y, r1.x, r1.y};
#pragma unroll
      for (int i = 0; i < 8; i++)
#pragma unroll
        for (int j = 0; j < 4; j++) acc[i][j] = ffma2(ap[i], bp[j], acc[i][j]);
    }
    __syncthreads();
  }
#pragma unroll
  for (int i = 0; i < 8; i++) {
    const int m = m0 + ty * 8 + i;
    float o[8];
#pragma unroll
    for (int j = 0; j < 4; j++) {
      o[2 * j + 0] = __uint_as_float((unsigned)(acc[i][j] & 0xffffffffull));
      o[2 * j + 1] = __uint_as_float((unsigned)(acc[i][j] >> 32));
    }
    *(float4*)&Yb[(size_t)m * HW + p0 + tx * 8]     = make_float4(o[0], o[1], o[2], o[3]);
    *(float4*)&Yb[(size_t)m * HW + p0 + tx * 8 + 4] = make_float4(o[4], o[5], o[6], o[7]);
  }
}

// ---------------------------------------------------------------------------
// Fused line-conv GEMM on tensor cores, split-bf16 (hi/lo, 3 MMAs).
// Y[m][p] = sum_{kg<4096} A[kg] * B_im2col[kg][p] + bias0[m]+bias1[m]
//   kg<2048:  vertical taps (w_attnx), rows shifted, reflect 256->254
//   kg>=2048: horizontal taps (w_attny), cols shifted, reflect 256->254
// Tile: 64(M) x 128(N), 256 threads = 8 warps (2x4 warp grid, 32x32/warp).
// ---------------------------------------------------------------------------
__global__ __launch_bounds__(256) void k_convmma(
    const float* __restrict__ A0, const float* __restrict__ A1,
    const float* __restrict__ bias0, const float* __restrict__ bias1,
    const float* __restrict__ X, float* __restrict__ Y) {
  __shared__ __nv_bfloat16 Ah[64][16], Al[64][16];
  __shared__ __nv_bfloat16 Bh[16][128], Bl[16][128];
  __shared__ float outbuf[64 * 128];

  const int b = blockIdx.z;
  const float* Xb = X + (size_t)b * C * HW;
  float* Yb = Y + (size_t)b * C * HW;
  const int m0 = blockIdx.x * 64;
  const int p0 = blockIdx.y * 128;   // within one image row (x0 in {0,128})
  const int y = p0 >> 8;
  const int x0 = p0 & 255;
  const int tid = threadIdx.x;
  const int wid = tid >> 5;
  const int warpM = wid >> 2;        // 0..1 -> m offset warpM*32
  const int warpN = wid & 3;         // 0..3 -> n offset warpN*32
  const int ar = tid >> 2, ak = (tid & 3) * 4;   // A loader: 64x16, 4/thread
  const int br = tid >> 4, bc0 = (tid & 15) * 8; // B loader: 16x128, 8/thread

  wmma::fragment<wmma::accumulator, 16, 16, 16, float> acc[2][2];
#pragma unroll
  for (int mi = 0; mi < 2; mi++)
#pragma unroll
    for (int ni = 0; ni < 2; ni++) wmma::fill_fragment(acc[mi][ni], 0.0f);

  for (int k0 = 0; k0 < 4096; k0 += 16) {
    // ---- A chunk [64][16]: fp32 -> bf16 hi/lo ----
    {
      const int kg = k0 + ak;   // chunk never straddles the 2048 boundary
      const float* src = (kg < 2048)
          ? A0 + (size_t)(m0 + ar) * 2048 + kg
          : A1 + (size_t)(m0 + ar) * 2048 + (kg - 2048);
      float4 v = *(const float4*)src;
      float vv[4] = {v.x, v.y, v.z, v.w};
#pragma unroll
      for (int q = 0; q < 4; q++) {
        __nv_bfloat16 h = __float2bfloat16(vv[q]);
        Ah[ar][ak + q] = h;
        Al[ar][ak + q] = __float2bfloat16(vv[q] - __bfloat162float(h));
      }
    }
    // ---- B chunk [16][128]: im2col fp32 -> bf16 hi/lo ----
    {
      const int kg = k0 + br;
      const int part = kg >> 11;
      const int kk = kg & 2047;
      const int c = kk >> 3, t = kk & 7;
      const float* ch = Xb + (size_t)c * HW;
      float v[8];
      if (part == 0) {  // vertical taps
        const int r = y + t - 3;
        if (r >= 0 && r <= 256) {
          const int rr = (r == 256) ? 254 : r;
          float4 f0 = *(const float4*)&ch[rr * 256 + x0 + bc0];
          float4 f1 = *(const float4*)&ch[rr * 256 + x0 + bc0 + 4];
          v[0] = f0.x; v[1] = f0.y; v[2] = f0.z; v[3] = f0.w;
          v[4] = f1.x; v[5] = f1.y; v[6] = f1.z; v[7] = f1.w;
        } else {
#pragma unroll
          for (int ii = 0; ii < 8; ii++) v[ii] = 0.f;
        }
      } else {          // horizontal taps
        const float* row = ch + y * 256;
        const int cbase = x0 + bc0 + t - 3;
#pragma unroll
        for (int ii = 0; ii < 8; ii++) {
          const int cc = cbase + ii;
          v[ii] = (cc >= 0 && cc <= 256) ? row[(cc == 256) ? 254 : cc] : 0.f;
        }
      }
#pragma unroll
      for (int q = 0; q < 8; q++) {
        __nv_bfloat16 h = __float2bfloat16(v[q]);
        Bh[br][bc0 + q] = h;
        Bl[br][bc0 + q] = __float2bfloat16(v[q] - __bfloat162float(h));
      }
    }
    __syncthreads();
    // ---- tensor-core MMAs: Ah*Bh + Ah*Bl + Al*Bh ----
    wmma::fragment<wmma::matrix_a, 16, 16, 16, __nv_bfloat16, wmma::row_major> ah[2], al[2];
    wmma::fragment<wmma::matrix_b, 16, 16, 16, __nv_bfloat16, wmma::row_major> bh[2], bl[2];
#pragma unroll
    for (int mi = 0; mi < 2; mi++) {
      wmma::load_matrix_sync(ah[mi], &Ah[warpM * 32 + mi * 16][0], 16);
      wmma::load_matrix_sync(al[mi], &Al[warpM * 32 + mi * 16][0], 16);
    }
#pragma unroll
    for (int ni = 0; ni < 2; ni++) {
      wmma::load_matrix_sync(bh[ni], &Bh[0][warpN * 32 + ni * 16], 128);
      wmma::load_matrix_sync(bl[ni], &Bl[0][warpN * 32 + ni * 16], 128);
    }
#pragma unroll
    for (int mi = 0; mi < 2; mi++)
#pragma unroll
      for (int ni = 0; ni < 2; ni++) {
        wmma::mma_sync(acc[mi][ni], ah[mi], bh[ni], acc[mi][ni]);
        wmma::mma_sync(acc[mi][ni], ah[mi], bl[ni], acc[mi][ni]);
        wmma::mma_sync(acc[mi][ni], al[mi], bh[ni], acc[mi][ni]);
      }
    __syncthreads();
  }
  // ---- epilogue: frags -> smem, add bias, write out ----
#pragma unroll
  for (int mi = 0; mi < 2; mi++)
#pragma unroll
    for (int ni = 0; ni < 2; ni++)
      wmma::store_matrix_sync(
          &outbuf[(warpM * 32 + mi * 16) * 128 + warpN * 32 + ni * 16],
          acc[mi][ni], 128, wmma::mem_row_major);
  __syncthreads();
  for (int idx = tid; idx < 64 * 128; idx += 256) {
    const int m = idx >> 7, n = idx & 127;
    const int mg = m0 + m;
    Yb[(size_t)mg * HW + p0 + n] = outbuf[idx] + bias0[mg] + bias1[mg];
  }
}

// ---------------------------------------------------------------------------
// Window attention — unchanged (verified).
// ---------------------------------------------------------------------------
__global__ __launch_bounds__(64) void k_attn(
    const float* __restrict__ qkv, const float* __restrict__ rel_table,
    float* __restrict__ o) {
  const int n = blockIdx.x;
  const int h = blockIdx.y;
  const int i = threadIdx.x;
  __shared__ float ks[64][17];
  __shared__ float vs[64][17];
  __shared__ float rt[225];
  const int b = n >> 10;
  const int rem = n & 1023;
  const int hh = rem >> 5, ww = rem & 31;
  const int yy = i >> 3, xx = i & 7;
  const int py = hh * 8 + yy, px = ww * 8 + xx;
  const size_t base = ((size_t)b * 3 * C + h * DH) * HW + py * 256 + px;
  const float scale = 0.25f;
  float q[16];
#pragma unroll
  for (int dc = 0; dc < 16; dc++) q[dc] = qkv[base + (size_t)dc * HW] * scale;
#pragma unroll
  for (int dc = 0; dc < 16; dc++) ks[i][dc] = qkv[base + (size_t)(C + dc) * HW];
#pragma unroll
  for (int dc = 0; dc < 16; dc++) vs[i][dc] = qkv[base + (size_t)(2 * C + dc) * HW];
  for (int t = i; t < 225; t += 64) rt[t] = rel_table[t * NH + h];
  __syncthreads();

  float p[64];
  float mx = -1e30f;
#pragma unroll
  for (int j = 0; j < 64; j++) {
    const int yj = j >> 3, xj = j & 7;
    float s = 0.f;
#pragma unroll
    for (int dc = 0; dc < 16; dc++) s += q[dc] * ks[j][dc];
    s += rt[(yy - yj + 7) * 15 + (xx - xj + 7)];
    p[j] = s;
    mx = fmaxf(mx, s);
  }
  float sum = 0.f;
#pragma unroll
  for (int j = 0; j < 64; j++) { p[j] = __expf(p[j] - mx); sum += p[j]; }
  const float inv = 1.f / sum;
  const size_t obase = ((size_t)b * C + h * DH) * HW + py * 256 + px;
#pragma unroll
  for (int dc = 0; dc < 16; dc++) {
    float a = 0.f;
#pragma unroll
    for (int j = 0; j < 64; j++) a += p[j] * vs[j][dc];
    o[obase + (size_t)dc * HW] = a * inv;
  }
}

// ---------------------------------------------------------------------------
// Depthwise 8x8 conv + BN — unchanged (verified).
// ---------------------------------------------------------------------------
__global__ void k_dwbn(const float* __restrict__ In, const float* __restrict__ w_dw,
                       const float* __restrict__ gamma, const float* __restrict__ beta,
                       const float* __restrict__ mean, const float* __restrict__ var,
                       float* __restrict__ Out) {
  const int x = blockIdx.x * 32 + threadIdx.x;
  const int y = blockIdx.y * 8 + threadIdx.y;
  const int bc = blockIdx.z;
  const int c = bc & 255;
  const float* in = In + (size_t)bc * HW;
  const float* wdc = w_dw + c * 64;
  float acc = 0.f;
#pragma unroll
  for (int ty2 = 0; ty2 < 8; ty2++) {
    const int r = y + ty2 - 3;
    if (r < 0 || r > 256) continue;
    const int rr = (r == 256) ? 254 : r;
    const float* row = in + rr * 256;
#pragma unroll
    for (int tx2 = 0; tx2 < 8; tx2++) {
      const int cc = x + tx2 - 3;
      if (cc < 0 || cc > 256) continue;
      acc += wdc[ty2 * 8 + tx2] * row[(cc == 256) ? 254 : cc];
    }
  }
  const float sc = gamma[c] / sqrtf(var[c] + 1e-5f);
  Out[(size_t)bc * HW + y * 256 + x] = (acc - mean[c]) * sc + beta[c];
}

// ---------------------------------------------------------------------------
extern "C" void kernel_launch(void* const* d_in, const int* in_sizes, int n_in,
                              void* d_out, int out_size) {
  const float* x         = (const float*)d_in[0];
  const float* w_qkv     = (const float*)d_in[1];
  const float* rel_table = (const float*)d_in[2];
  const float* w_attnx   = (const float*)d_in[3];
  const float* b_attnx   = (const float*)d_in[4];
  const float* w_attny   = (const float*)d_in[5];
  const float* b_attny   = (const float*)d_in[6];
  const float* w_dw      = (const float*)d_in[7];
  const float* bn_gamma  = (const float*)d_in[8];
  const float* bn_beta   = (const float*)d_in[9];
  const float* bn_mean   = (const float*)d_in[10];
  const float* bn_var    = (const float*)d_in[11];
  const float* w_proj    = (const float*)d_in[12];
  float* out = (float*)d_out;

  float *qkvp, *op, *xyp, *bnp;
  cudaGetSymbolAddress((void**)&qkvp, g_qkv);
  cudaGetSymbolAddress((void**)&op,   g_o);
  cudaGetSymbolAddress((void**)&xyp,  g_xy);
  cudaGetSymbolAddress((void**)&bnp,  g_bn);

  // 1) qkv 1x1: [768,256] @ [256,65536] per batch
  k_gemm0<<<dim3(6, 512, 2), 256>>>(w_qkv, x, qkvp, 3 * C);
  // 2) window attention
  k_attn<<<dim3(2048, 16), 64>>>(qkvp, rel_table, op);
  // 3) fused attn-x + attn-y line convs on TENSOR CORES (split-bf16, K=4096)
  k_convmma<<<dim3(4, 512, 2), 256>>>(w_attnx, w_attny, b_attnx, b_attny, op, xyp);
  // 4) depthwise 8x8 + BN
  k_dwbn<<<dim3(8, 32, BATCH * C), dim3(32, 8)>>>(xyp, w_dw, bn_gamma, bn_beta,
                                                  bn_mean, bn_var, bnp);
  // 5) final 1x1 projection -> d_out
  k_gemm0<<<dim3(2, 512, 2), 256>>>(w_proj, bnp, out, C);
}